// round 3
// baseline (speedup 1.0000x reference)
#include <cuda_runtime.h>
#include <cuda_bf16.h>
#include <math.h>

// Problem constants
#define B_   1024
#define H_   256
#define HP_  128

// Scratch (static device arrays; no allocation allowed)
__device__ float g_x3[B_ * HP_];      // tanh-chain output  [1024,128]
__device__ float g_g1out[B_ * H_];    // phase-A output     [1024,256]

// ---------------------------------------------------------------------------
// K0: h = cc*h0 + (1-cc)*ht ; x1 = tanh(h @ fc1^T); x2 = tanh(x1 @ fc2^T);
//     x3 = tanh(x2 @ fc3^T)
// One block handles 8 batch rows; 128 threads (one per output neuron).
// ---------------------------------------------------------------------------
__global__ __launch_bounds__(128) void prep_kernel(
    const float* __restrict__ h0, const float* __restrict__ ht,
    const float* __restrict__ cp,
    const float* __restrict__ fc1, const float* __restrict__ fc2,
    const float* __restrict__ fc3, float* __restrict__ x3out)
{
    __shared__ float sh[8][256];
    __shared__ float s1[8][128];
    __shared__ float s2[8][128];

    const int t  = threadIdx.x;      // 0..127 = output neuron
    const int b0 = blockIdx.x * 8;

    float cc = cp[0];
    cc = fminf(fmaxf(cc, 0.0f), 1.0f);

    // load + blend h for 8 rows (coalesced)
    for (int i = t; i < 8 * 256; i += 128) {
        int bb = i >> 8, j = i & 255;
        int g = (b0 + bb) * 256 + j;
        sh[bb][j] = cc * h0[g] + (1.0f - cc) * ht[g];
    }
    __syncthreads();

    // x1 = tanh(fc1 row t . h)
    {
        float acc[8] = {0,0,0,0,0,0,0,0};
        const float4* wr = (const float4*)(fc1 + t * 256);
        #pragma unroll 8
        for (int j4 = 0; j4 < 64; ++j4) {
            float4 w = wr[j4];
            int j = j4 * 4;
            #pragma unroll
            for (int bb = 0; bb < 8; ++bb) {
                acc[bb] += w.x * sh[bb][j]   + w.y * sh[bb][j+1]
                         + w.z * sh[bb][j+2] + w.w * sh[bb][j+3];
            }
        }
        #pragma unroll
        for (int bb = 0; bb < 8; ++bb) s1[bb][t] = tanhf(acc[bb]);
    }
    __syncthreads();

    // x2 = tanh(fc2 row t . x1)
    {
        float acc[8] = {0,0,0,0,0,0,0,0};
        const float4* wr = (const float4*)(fc2 + t * 128);
        #pragma unroll 8
        for (int j4 = 0; j4 < 32; ++j4) {
            float4 w = wr[j4];
            int j = j4 * 4;
            #pragma unroll
            for (int bb = 0; bb < 8; ++bb) {
                acc[bb] += w.x * s1[bb][j]   + w.y * s1[bb][j+1]
                         + w.z * s1[bb][j+2] + w.w * s1[bb][j+3];
            }
        }
        #pragma unroll
        for (int bb = 0; bb < 8; ++bb) s2[bb][t] = tanhf(acc[bb]);
    }
    __syncthreads();

    // x3 = tanh(fc3 row t . x2) -> global
    {
        float acc[8] = {0,0,0,0,0,0,0,0};
        const float4* wr = (const float4*)(fc3 + t * 128);
        #pragma unroll 8
        for (int j4 = 0; j4 < 32; ++j4) {
            float4 w = wr[j4];
            int j = j4 * 4;
            #pragma unroll
            for (int bb = 0; bb < 8; ++bb) {
                acc[bb] += w.x * s2[bb][j]   + w.y * s2[bb][j+1]
                         + w.z * s2[bb][j+2] + w.w * s2[bb][j+3];
            }
        }
        #pragma unroll
        for (int bb = 0; bb < 8; ++bb)
            x3out[(b0 + bb) * 128 + t] = tanhf(acc[bb]);
    }
}

// ---------------------------------------------------------------------------
// Phase kernel (used for both hyper-applications):
//   pre[b, j] = sum_{h=0..255} left[b,h] * ( sum_{r=0..127} x3[b,r] * W[(j*256+h)*128 + r] )
//   out[b, j] = TANH ? tanh(pre) : pre
//
// Phase A: left = msg,    W = fc4_w (first half),  out = g_g1out (tanh)
// Phase B: left = g_g1out,W = fc4_w + 256*256*128, out = d_out   (no tanh)
//
// Tiling: block = 256 threads computes [64 b x 8 j]; thread = (b_sub = tid&63,
// q = tid>>6) owning r-range [q*32, q*32+32). x3 slice lives in registers.
// Loop over h with double-buffered W tile (8 rows x 128) in smem.
// ---------------------------------------------------------------------------
#define SMEM_PHASE_BYTES (64 * 257 * 4 + 2 * 8 * 128 * 4)

template <bool TANH>
__global__ __launch_bounds__(256, 2) void phase_kernel(
    const float* __restrict__ left,   // [1024, 256]
    const float* __restrict__ x3g,    // [1024, 128]
    const float* __restrict__ Wbase,  // rows (j*256+h), 128 cols
    float* __restrict__ outp)         // [1024, 256]
{
    extern __shared__ float smem[];
    float* s_left = smem;                   // [64][257] padded
    float* s_w    = smem + 64 * 257;        // [2][8][128]
    float* s_red  = s_w;                    // reuse after mainloop: [4][64][8]

    const int tid   = threadIdx.x;
    const int b_sub = tid & 63;
    const int q     = tid >> 6;             // 0..3
    const int kt    = blockIdx.x & 31;      // 32 j-tiles
    const int bt    = blockIdx.x >> 5;      // 16 b-tiles
    const int j0    = kt * 8;
    const int b0    = bt * 64;

    // stage left tile [64 x 256] (coalesced)
    for (int i = tid; i < 64 * 256; i += 256) {
        int bb = i >> 8, hh = i & 255;
        s_left[bb * 257 + hh] = left[(b0 + bb) * 256 + hh];
    }

    // x3 slice -> registers (32 floats)
    float xr[32];
    {
        const float4* xp = (const float4*)(x3g + (b0 + b_sub) * 128 + q * 32);
        #pragma unroll
        for (int j = 0; j < 8; ++j) {
            float4 v = xp[j];
            xr[4*j+0] = v.x; xr[4*j+1] = v.y; xr[4*j+2] = v.z; xr[4*j+3] = v.w;
        }
    }

    // W loader: each thread loads one float4 per h.
    // warp w (=tid>>5) loads row j0+w ; lane loads 16B chunk -> coalesced.
    const int wrow  = tid >> 5;          // 0..7
    const int wcol4 = (tid & 31) * 4;    // 0..124

    // preload h = 0 into buffer 0
    {
        const float4 v = *(const float4*)(Wbase + ((j0 + wrow) * 256 + 0) * 128 + wcol4);
        *(float4*)(s_w + 0 * 1024 + wrow * 128 + wcol4) = v;
    }
    __syncthreads();

    float acc[8] = {0,0,0,0,0,0,0,0};

    for (int h = 0; h < 256; ++h) {
        const int cur = h & 1;
        float4 nw;
        const bool has = (h + 1) < 256;
        if (has) {
            nw = *(const float4*)(Wbase + ((j0 + wrow) * 256 + (h + 1)) * 128 + wcol4);
        }

        const float m = s_left[b_sub * 257 + h];
        const float* wb = s_w + cur * 1024;
        #pragma unroll
        for (int kk = 0; kk < 8; ++kk) {
            const float4* wp = (const float4*)(wb + kk * 128 + q * 32);
            float tsum = 0.0f;
            #pragma unroll
            for (int j = 0; j < 8; ++j) {
                float4 w = wp[j];
                tsum += w.x * xr[4*j+0] + w.y * xr[4*j+1]
                      + w.z * xr[4*j+2] + w.w * xr[4*j+3];
            }
            acc[kk] += m * tsum;
        }

        if (has) {
            *(float4*)(s_w + ((h + 1) & 1) * 1024 + wrow * 128 + wcol4) = nw;
        }
        __syncthreads();
    }

    // cross-q reduction via smem (s_w region is free now; last sync done above)
    #pragma unroll
    for (int kk = 0; kk < 8; ++kk)
        s_red[q * 512 + b_sub * 8 + kk] = acc[kk];
    __syncthreads();

    for (int o = tid; o < 512; o += 256) {
        const int bb = o >> 3, kk = o & 7;
        float s = s_red[0   + bb * 8 + kk] + s_red[512  + bb * 8 + kk]
                + s_red[1024 + bb * 8 + kk] + s_red[1536 + bb * 8 + kk];
        if (TANH) s = tanhf(s);
        outp[(b0 + bb) * 256 + (j0 + kk)] = s;
    }
}

// ---------------------------------------------------------------------------
extern "C" void kernel_launch(void* const* d_in, const int* in_sizes, int n_in,
                              void* d_out, int out_size)
{
    const float* h0   = (const float*)d_in[0];
    const float* ht   = (const float*)d_in[1];
    const float* msg  = (const float*)d_in[2];
    const float* cp   = (const float*)d_in[3];
    const float* fc1  = (const float*)d_in[4];
    const float* fc2  = (const float*)d_in[5];
    const float* fc3  = (const float*)d_in[6];
    const float* fc4  = (const float*)d_in[7];
    float*       outp = (float*)d_out;

    float* x3p;    cudaGetSymbolAddress((void**)&x3p,    g_x3);
    float* g1p;    cudaGetSymbolAddress((void**)&g1p,    g_g1out);

    cudaFuncSetAttribute(phase_kernel<true>,
                         cudaFuncAttributeMaxDynamicSharedMemorySize, SMEM_PHASE_BYTES);
    cudaFuncSetAttribute(phase_kernel<false>,
                         cudaFuncAttributeMaxDynamicSharedMemorySize, SMEM_PHASE_BYTES);

    // K0: tanh chain -> g_x3
    prep_kernel<<<128, 128>>>(h0, ht, cp, fc1, fc2, fc3, x3p);

    // Phase A: g1_out = tanh( msg x3 : W1 )
    phase_kernel<true><<<512, 256, SMEM_PHASE_BYTES>>>(msg, x3p, fc4, g1p);

    // Phase B: out = ( g1_out x3 : W2 )
    const float* fc4b = fc4 + (size_t)H_ * H_ * HP_;   // + 256*256*128
    phase_kernel<false><<<512, 256, SMEM_PHASE_BYTES>>>(g1p, x3p, fc4b, outp);
}

// round 7
// speedup vs baseline: 4.6224x; 4.6224x over previous
#include <cuda_runtime.h>
#include <cuda_fp16.h>
#include <math.h>
#include <stdint.h>

#define B_   1024
#define H_   256
#define HP_  128
#define PHASE_W 8388608   // 256*32768 elements per phase
#define NSPLIT  8

// ---------------- scratch (static device arrays; no allocation) -------------
__device__ float  g_x3[B_ * HP_];          // [1024,128]
__device__ float  g_g1out[B_ * H_];        // [1024,256]
__device__ __half g_whi[2 * PHASE_W];      // 33.5 MB
__device__ __half g_wlo[2 * PHASE_W];      // 33.5 MB
__device__ float  g_part[NSPLIT * B_ * H_]; // split-K partials, 8 MB

// ---------------- helpers ----------------------------------------------------
#define SWZ(o) ((o) ^ (((o) >> 3) & 0x70))

static __device__ __forceinline__ uint32_t smem_u32(const void* p) {
    return (uint32_t)__cvta_generic_to_shared(p);
}

#define LDSM_X4(r, addr)                                                        \
    asm volatile("ldmatrix.sync.aligned.m8n8.x4.shared.b16 {%0,%1,%2,%3}, [%4];"\
        : "=r"((r)[0]), "=r"((r)[1]), "=r"((r)[2]), "=r"((r)[3]) : "r"(addr))

#define MMA16816(d, a, b0v, b1v)                                                \
    asm volatile("mma.sync.aligned.m16n8k16.row.col.f32.f16.f16.f32 "           \
        "{%0,%1,%2,%3}, {%4,%5,%6,%7}, {%8,%9}, {%0,%1,%2,%3};"                 \
        : "+f"((d)[0]), "+f"((d)[1]), "+f"((d)[2]), "+f"((d)[3])                \
        : "r"((a)[0]), "r"((a)[1]), "r"((a)[2]), "r"((a)[3]),                   \
          "r"(b0v), "r"(b1v))

#define CP_ASYNC16(dst, src)                                                    \
    asm volatile("cp.async.cg.shared.global [%0], [%1], 16;"                    \
                 :: "r"(dst), "l"(src))
#define CP_COMMIT() asm volatile("cp.async.commit_group;" ::: "memory")

// ---------------------------------------------------------------------------
// W convert: fp32 -> fp16 hi/lo (once per launch, both phases)
// ---------------------------------------------------------------------------
__global__ __launch_bounds__(512) void convert_w(
    const float* __restrict__ w, __half* __restrict__ whi,
    __half* __restrict__ wlo)
{
    const int total4 = (2 * PHASE_W) / 4;
    for (int i = blockIdx.x * blockDim.x + threadIdx.x; i < total4;
         i += gridDim.x * blockDim.x) {
        float4 v = ((const float4*)w)[i];
        __half h0 = __float2half_rn(v.x), h1 = __float2half_rn(v.y);
        __half h2 = __float2half_rn(v.z), h3 = __float2half_rn(v.w);
        __half l0 = __float2half_rn(v.x - __half2float(h0));
        __half l1 = __float2half_rn(v.y - __half2float(h1));
        __half l2 = __float2half_rn(v.z - __half2float(h2));
        __half l3 = __float2half_rn(v.w - __half2float(h3));
        __half2 ph0 = __halves2half2(h0, h1), ph1 = __halves2half2(h2, h3);
        __half2 pl0 = __halves2half2(l0, l1), pl1 = __halves2half2(l2, l3);
        ((uint2*)whi)[i] = make_uint2(*(uint32_t*)&ph0, *(uint32_t*)&ph1);
        ((uint2*)wlo)[i] = make_uint2(*(uint32_t*)&pl0, *(uint32_t*)&pl1);
    }
}

// ---------------------------------------------------------------------------
// K0: blend + 3-layer tanh MLP -> x3. 4 batch rows per block, grid 256.
// ---------------------------------------------------------------------------
__global__ __launch_bounds__(128) void prep_kernel(
    const float* __restrict__ h0, const float* __restrict__ ht,
    const float* __restrict__ cp,
    const float* __restrict__ fc1, const float* __restrict__ fc2,
    const float* __restrict__ fc3, float* __restrict__ x3out)
{
    __shared__ float sh[4][256];
    __shared__ float s1[4][128];
    __shared__ float s2[4][128];
    const int t = threadIdx.x;
    const int b0 = blockIdx.x * 4;
    float cc = fminf(fmaxf(cp[0], 0.0f), 1.0f);
    for (int i = t; i < 4 * 256; i += 128) {
        int bb = i >> 8, j = i & 255;
        int g = (b0 + bb) * 256 + j;
        sh[bb][j] = cc * h0[g] + (1.0f - cc) * ht[g];
    }
    __syncthreads();
    {
        float acc[4] = {0, 0, 0, 0};
        const float4* wr = (const float4*)(fc1 + t * 256);
        #pragma unroll 8
        for (int j4 = 0; j4 < 64; ++j4) {
            float4 w = wr[j4]; int j = j4 * 4;
            #pragma unroll
            for (int bb = 0; bb < 4; ++bb)
                acc[bb] += w.x*sh[bb][j] + w.y*sh[bb][j+1] + w.z*sh[bb][j+2] + w.w*sh[bb][j+3];
        }
        #pragma unroll
        for (int bb = 0; bb < 4; ++bb) s1[bb][t] = tanhf(acc[bb]);
    }
    __syncthreads();
    {
        float acc[4] = {0, 0, 0, 0};
        const float4* wr = (const float4*)(fc2 + t * 128);
        #pragma unroll 8
        for (int j4 = 0; j4 < 32; ++j4) {
            float4 w = wr[j4]; int j = j4 * 4;
            #pragma unroll
            for (int bb = 0; bb < 4; ++bb)
                acc[bb] += w.x*s1[bb][j] + w.y*s1[bb][j+1] + w.z*s1[bb][j+2] + w.w*s1[bb][j+3];
        }
        #pragma unroll
        for (int bb = 0; bb < 4; ++bb) s2[bb][t] = tanhf(acc[bb]);
    }
    __syncthreads();
    {
        float acc[4] = {0, 0, 0, 0};
        const float4* wr = (const float4*)(fc3 + t * 128);
        #pragma unroll 8
        for (int j4 = 0; j4 < 32; ++j4) {
            float4 w = wr[j4]; int j = j4 * 4;
            #pragma unroll
            for (int bb = 0; bb < 4; ++bb)
                acc[bb] += w.x*s2[bb][j] + w.y*s2[bb][j+1] + w.z*s2[bb][j+2] + w.w*s2[bb][j+3];
        }
        #pragma unroll
        for (int bb = 0; bb < 4; ++bb)
            x3out[(b0 + bb) * 128 + t] = tanhf(acc[bb]);
    }
}

// ---------------------------------------------------------------------------
// Hyper-GEMM via mma.sync (fp16, W 2-term hi/lo compensation):
//   part[ks][b0:b0+256, j0:j0+64] += A @ (Whi + Wlo)^T over this K split,
//   A[b, h*128+r] = left[b,h]*x3[b,r] synthesized into smem as fp16.
// Grid: 128 = 4 mt x 4 nt x 8 ks. K/split = 4096 = 64 chunks of 64.
// Block: 256 threads = 8 warps (4 M-warps x 2 N-warps; warp tile 64x32).
// ---------------------------------------------------------------------------
#define STAGE_BYTES 49152
#define A_OFF       0
#define WHI_OFF     32768
#define WLO_OFF     40960
#define X3_OFF      (2 * STAGE_BYTES)             // [256][65] u32 (h2), 66560 B
#define LEFT_OFF    (X3_OFF + 256 * 65 * 4)       // [256][33] f32, 33792 B
#define GEMM_SMEM   (LEFT_OFF + 256 * 33 * 4)     // 198656 B

__global__ __launch_bounds__(256, 1) void hyper_gemm(
    const float* __restrict__ left,          // [1024,256]
    const float* __restrict__ x3g,           // [1024,128]
    const __half* __restrict__ whi,          // [256][32768]
    const __half* __restrict__ wlo,
    float* __restrict__ part)                // [8][1024][256]
{
    extern __shared__ char smem[];
    const uint32_t smb = smem_u32(smem);
    const int t = threadIdx.x;

    const int mt = blockIdx.x & 3;
    const int nt = (blockIdx.x >> 2) & 3;
    const int ks = blockIdx.x >> 4;
    const int b0 = mt * 256;
    const int j0 = nt * 64;
    const int k_base = ks * 4096;
    const int h_base = ks * 32;

    uint32_t* s_x3  = (uint32_t*)(smem + X3_OFF);
    float*    s_left = (float*)(smem + LEFT_OFF);

    // ---- stage left slab [256][32] (padded 33) ----
    #pragma unroll
    for (int u = 0; u < 8; ++u) {
        int id = u * 256 + t;                 // 2048 float4
        int r = id >> 3, c4 = id & 7;
        float4 v = *(const float4*)(left + (size_t)(b0 + r) * 256 + h_base + c4 * 4);
        float* dp = s_left + r * 33 + c4 * 4;
        dp[0] = v.x; dp[1] = v.y; dp[2] = v.z; dp[3] = v.w;
    }
    // ---- stage x3 slab [256][128] as h2 words, pitch 65 (conflict-free) ----
    #pragma unroll
    for (int u = 0; u < 32; ++u) {
        int id = u * 256 + t;                 // 8192 float4
        int r = id >> 5, c4 = id & 31;
        float4 v = *(const float4*)(x3g + (size_t)(b0 + r) * 128 + c4 * 4);
        __half2 p0 = __floats2half2_rn(v.x, v.y);
        __half2 p1 = __floats2half2_rn(v.z, v.w);
        s_x3[r * 65 + c4 * 2]     = *(uint32_t*)&p0;
        s_x3[r * 65 + c4 * 2 + 1] = *(uint32_t*)&p1;
    }
    __syncthreads();

    // ---- producer: A-gen + W cp.async for chunk c into stage s ----
    #define PRODUCE(c, s) do {                                                    \
        char* stg = smem + (s) * STAGE_BYTES;                                     \
        const float L = s_left[t * 33 + ((c) >> 1)];                              \
        const uint32_t xoff = t * 65 + ((c) & 1) * 32;                            \
        _Pragma("unroll")                                                         \
        for (int u = 0; u < 8; ++u) {                                             \
            uint32_t o[4];                                                        \
            _Pragma("unroll")                                                     \
            for (int w2 = 0; w2 < 4; ++w2) {                                      \
                uint32_t xp = s_x3[xoff + u * 4 + w2];                            \
                __half2 xh = *(__half2*)&xp;                                      \
                __half2 rr = __floats2half2_rn(L * __low2float(xh),               \
                                               L * __high2float(xh));             \
                o[w2] = *(uint32_t*)&rr;                                          \
            }                                                                     \
            int off = t * 128 + u * 16;                                           \
            *(uint4*)(stg + A_OFF + SWZ(off)) = make_uint4(o[0], o[1], o[2], o[3]);\
        }                                                                         \
        const int kg = k_base + (c) * 64;                                         \
        _Pragma("unroll")                                                         \
        for (int u = 0; u < 4; ++u) {                                             \
            int id = u * 256 + t;                                                 \
            int half = id >> 9, rid = id & 511;                                   \
            int row = rid >> 3, c16 = rid & 7;                                    \
            const __half* src = (half ? wlo : whi)                                \
                + (size_t)(j0 + row) * 32768 + kg + c16 * 8;                      \
            int off = row * 128 + c16 * 16;                                       \
            uint32_t dst = smb + (s) * STAGE_BYTES                                \
                + (half ? WLO_OFF : WHI_OFF) + SWZ(off);                          \
            CP_ASYNC16(dst, src);                                                 \
        }                                                                         \
        CP_COMMIT();                                                              \
    } while (0)

    // ---- consumer state ----
    const int wid = t >> 5, l = t & 31;
    const int mw = wid & 3;         // M-warp: rows mw*64 .. +64
    const int nw = wid >> 2;        // N-warp: cols nw*32 .. +32
    float d[4][4][4];
    #pragma unroll
    for (int mi = 0; mi < 4; ++mi)
        #pragma unroll
        for (int ni = 0; ni < 4; ++ni)
            #pragma unroll
            for (int e = 0; e < 4; ++e) d[mi][ni][e] = 0.0f;

    const uint32_t lrow = (uint32_t)(l & 15);
    const uint32_t lkb  = (uint32_t)((l >> 4) * 16);

    PRODUCE(0, 0);
    PRODUCE(1, 1);

    for (int c = 0; c < 64; ++c) {
        const int s = c & 1;
        if (c < 62) asm volatile("cp.async.wait_group 1;" ::: "memory");
        else        asm volatile("cp.async.wait_group 0;" ::: "memory");
        __syncthreads();

        const uint32_t aB = smb + s * STAGE_BYTES + A_OFF;
        const uint32_t hB = smb + s * STAGE_BYTES + WHI_OFF;
        const uint32_t lB = smb + s * STAGE_BYTES + WLO_OFF;

        #pragma unroll
        for (int st = 0; st < 4; ++st) {
            const uint32_t kb = st * 32 + lkb;
            uint32_t a[4][4], bh[2][4], bl[2][4];
            #pragma unroll
            for (int mi = 0; mi < 4; ++mi) {
                uint32_t off = (mw * 64 + mi * 16 + lrow) * 128 + kb;
                LDSM_X4(a[mi], aB + SWZ(off));
            }
            #pragma unroll
            for (int nb = 0; nb < 2; ++nb) {
                uint32_t off = (nw * 32 + nb * 16 + lrow) * 128 + kb;
                LDSM_X4(bh[nb], hB + SWZ(off));
                LDSM_X4(bl[nb], lB + SWZ(off));
            }
            #pragma unroll
            for (int mi = 0; mi < 4; ++mi)
                #pragma unroll
                for (int ni = 0; ni < 4; ++ni) {
                    const int x4i = ni >> 1, pr = ni & 1;
                    MMA16816(d[mi][ni], a[mi], bh[x4i][pr], bh[x4i][pr + 2]);
                    MMA16816(d[mi][ni], a[mi], bl[x4i][pr], bl[x4i][pr + 2]);
                }
        }
        __syncthreads();
        if (c + 2 < 64) PRODUCE(c + 2, s);
    }

    // ---- epilogue: write fp32 partials ----
    {
        float* op = part + (size_t)ks * (B_ * H_);
        const int rb = b0 + mw * 64;
        const int cb = j0 + nw * 32;
        #pragma unroll
        for (int mi = 0; mi < 4; ++mi)
            #pragma unroll
            for (int ni = 0; ni < 4; ++ni) {
                int row = rb + mi * 16 + (l >> 2);
                int col = cb + ni * 8 + (l & 3) * 2;
                *(float2*)(op + (size_t)row * 256 + col) =
                    make_float2(d[mi][ni][0], d[mi][ni][1]);
                *(float2*)(op + (size_t)(row + 8) * 256 + col) =
                    make_float2(d[mi][ni][2], d[mi][ni][3]);
            }
    }
    #undef PRODUCE
}

// ---------------------------------------------------------------------------
// Split-K reduction over 8 partials (+ optional tanh)
// ---------------------------------------------------------------------------
template <bool TANH>
__global__ __launch_bounds__(256) void reduce8(
    const float* __restrict__ part, float* __restrict__ outp)
{
    const int total4 = (B_ * H_) / 4;   // 65536
    for (int i = blockIdx.x * blockDim.x + threadIdx.x; i < total4;
         i += gridDim.x * blockDim.x) {
        float4 r = ((const float4*)part)[i];
        #pragma unroll
        for (int s = 1; s < NSPLIT; ++s) {
            float4 v = ((const float4*)part)[i + s * 65536];
            r.x += v.x; r.y += v.y; r.z += v.z; r.w += v.w;
        }
        if (TANH) { r.x = tanhf(r.x); r.y = tanhf(r.y); r.z = tanhf(r.z); r.w = tanhf(r.w); }
        ((float4*)outp)[i] = r;
    }
}

// ---------------------------------------------------------------------------
extern "C" void kernel_launch(void* const* d_in, const int* in_sizes, int n_in,
                              void* d_out, int out_size)
{
    const float* h0  = (const float*)d_in[0];
    const float* ht  = (const float*)d_in[1];
    const float* msg = (const float*)d_in[2];
    const float* cp  = (const float*)d_in[3];
    const float* fc1 = (const float*)d_in[4];
    const float* fc2 = (const float*)d_in[5];
    const float* fc3 = (const float*)d_in[6];
    const float* fc4 = (const float*)d_in[7];
    float*       outp = (float*)d_out;

    float* x3p;  cudaGetSymbolAddress((void**)&x3p, g_x3);
    float* g1p;  cudaGetSymbolAddress((void**)&g1p, g_g1out);
    float* pp;   cudaGetSymbolAddress((void**)&pp,  g_part);
    __half* whi; cudaGetSymbolAddress((void**)&whi, g_whi);
    __half* wlo; cudaGetSymbolAddress((void**)&wlo, g_wlo);

    cudaFuncSetAttribute(hyper_gemm, cudaFuncAttributeMaxDynamicSharedMemorySize,
                         GEMM_SMEM);

    // W -> fp16 hi/lo (both phases)
    convert_w<<<2048, 512>>>(fc4, whi, wlo);
    // tanh chain -> x3
    prep_kernel<<<256, 128>>>(h0, ht, cp, fc1, fc2, fc3, x3p);
    // Phase A: g1_out = tanh(msg,x3 : W1)
    hyper_gemm<<<128, 256, GEMM_SMEM>>>(msg, x3p, whi, wlo, pp);
    reduce8<true><<<256, 256>>>(pp, g1p);
    // Phase B: out = (g1_out,x3 : W2)
    hyper_gemm<<<128, 256, GEMM_SMEM>>>(g1p, x3p, whi + PHASE_W, wlo + PHASE_W, pp);
    reduce8<false><<<256, 256>>>(pp, outp);
}

// round 8
// speedup vs baseline: 4.7033x; 1.0175x over previous
#include <cuda_runtime.h>
#include <cuda_fp16.h>
#include <math.h>
#include <stdint.h>

#define B_   1024
#define H_   256
#define HP_  128
#define PHASE_W 8388608   // 256*32768 elements per phase
#define NSPLIT  8

// ---------------- scratch (static device arrays; no allocation) -------------
__device__ float  g_x3[B_ * HP_];           // [1024,128]
__device__ float  g_g1out[B_ * H_];         // [1024,256]
__device__ float  g_part[NSPLIT * B_ * H_]; // split-K partials, 8 MB

// ---------------- helpers ----------------------------------------------------
#define SWZ(o) ((o) ^ (((o) >> 3) & 0x70))

static __device__ __forceinline__ uint32_t smem_u32(const void* p) {
    return (uint32_t)__cvta_generic_to_shared(p);
}
static __device__ __forceinline__ uint32_t h2bits(__half2 h) {
    return *(uint32_t*)&h;
}

#define LDSM_X4(r, addr)                                                        \
    asm volatile("ldmatrix.sync.aligned.m8n8.x4.shared.b16 {%0,%1,%2,%3}, [%4];"\
        : "=r"((r)[0]), "=r"((r)[1]), "=r"((r)[2]), "=r"((r)[3]) : "r"(addr))

#define MMA16816(d, a, b0v, b1v)                                                \
    asm volatile("mma.sync.aligned.m16n8k16.row.col.f32.f16.f16.f32 "           \
        "{%0,%1,%2,%3}, {%4,%5,%6,%7}, {%8,%9}, {%0,%1,%2,%3};"                 \
        : "+f"((d)[0]), "+f"((d)[1]), "+f"((d)[2]), "+f"((d)[3])                \
        : "r"((a)[0]), "r"((a)[1]), "r"((a)[2]), "r"((a)[3]),                   \
          "r"(b0v), "r"(b1v))

// ---------------------------------------------------------------------------
// K0: blend + 3-layer tanh MLP -> x3. 4 batch rows per block, grid 256.
// ---------------------------------------------------------------------------
__global__ __launch_bounds__(128) void prep_kernel(
    const float* __restrict__ h0, const float* __restrict__ ht,
    const float* __restrict__ cp,
    const float* __restrict__ fc1, const float* __restrict__ fc2,
    const float* __restrict__ fc3, float* __restrict__ x3out)
{
    __shared__ float sh[4][256];
    __shared__ float s1[4][128];
    __shared__ float s2[4][128];
    const int t = threadIdx.x;
    const int b0 = blockIdx.x * 4;
    float cc = fminf(fmaxf(cp[0], 0.0f), 1.0f);
    for (int i = t; i < 4 * 256; i += 128) {
        int bb = i >> 8, j = i & 255;
        int g = (b0 + bb) * 256 + j;
        sh[bb][j] = cc * h0[g] + (1.0f - cc) * ht[g];
    }
    __syncthreads();
    {
        float acc[4] = {0, 0, 0, 0};
        const float4* wr = (const float4*)(fc1 + t * 256);
        #pragma unroll 8
        for (int j4 = 0; j4 < 64; ++j4) {
            float4 w = wr[j4]; int j = j4 * 4;
            #pragma unroll
            for (int bb = 0; bb < 4; ++bb)
                acc[bb] += w.x*sh[bb][j] + w.y*sh[bb][j+1] + w.z*sh[bb][j+2] + w.w*sh[bb][j+3];
        }
        #pragma unroll
        for (int bb = 0; bb < 4; ++bb) s1[bb][t] = tanhf(acc[bb]);
    }
    __syncthreads();
    {
        float acc[4] = {0, 0, 0, 0};
        const float4* wr = (const float4*)(fc2 + t * 128);
        #pragma unroll 8
        for (int j4 = 0; j4 < 32; ++j4) {
            float4 w = wr[j4]; int j = j4 * 4;
            #pragma unroll
            for (int bb = 0; bb < 4; ++bb)
                acc[bb] += w.x*s1[bb][j] + w.y*s1[bb][j+1] + w.z*s1[bb][j+2] + w.w*s1[bb][j+3];
        }
        #pragma unroll
        for (int bb = 0; bb < 4; ++bb) s2[bb][t] = tanhf(acc[bb]);
    }
    __syncthreads();
    {
        float acc[4] = {0, 0, 0, 0};
        const float4* wr = (const float4*)(fc3 + t * 128);
        #pragma unroll 8
        for (int j4 = 0; j4 < 32; ++j4) {
            float4 w = wr[j4]; int j = j4 * 4;
            #pragma unroll
            for (int bb = 0; bb < 4; ++bb)
                acc[bb] += w.x*s2[bb][j] + w.y*s2[bb][j+1] + w.z*s2[bb][j+2] + w.w*s2[bb][j+3];
        }
        #pragma unroll
        for (int bb = 0; bb < 4; ++bb)
            x3out[(b0 + bb) * 128 + t] = tanhf(acc[bb]);
    }
}

// ---------------------------------------------------------------------------
// Hyper-GEMM via mma.sync, fp16 with W 2-term hi/lo compensation.
// W is read as fp32 and split to hi/lo in the producer (bit-identical to a
// separate convert, zero extra global traffic since fp32 == hi+lo in bytes).
//   part[ks][b0:b0+256, j0:j0+64] += A @ (Whi+Wlo)^T over this K split,
//   A[b, h*128+r] = left[b,h]*x3[b,r] synthesized in smem as fp16.
// Grid: 128 = 4 mt x 4 nt x 8 ks. K/split = 4096 = 64 chunks of 64.
// Block: 512 threads = 16 warps (4 M x 4 N; warp tile 64x16).
// 3 smem stages, one __syncthreads per chunk.
// ---------------------------------------------------------------------------
#define ST_BYTES   49152          // A 32K | Whi 8K | Wlo 8K
#define A_OFF      0
#define WHI_OFF    32768
#define WLO_OFF    40960
#define LEFT_OFF   (3 * ST_BYTES)                 // [256][33] f32 = 33792 B
#define GEMM_SMEM  (LEFT_OFF + 256 * 33 * 4)      // 181248 B

__global__ __launch_bounds__(512, 1) void hyper_gemm(
    const float* __restrict__ left,          // [1024,256]
    const float* __restrict__ x3g,           // [1024,128]
    const float* __restrict__ wf,            // fp32 [256][32768]
    float* __restrict__ part)                // [8][1024][256]
{
    extern __shared__ char smem[];
    const uint32_t smb = smem_u32(smem);
    const int t = threadIdx.x;

    const int mt = blockIdx.x & 3;
    const int nt = (blockIdx.x >> 2) & 3;
    const int ks = blockIdx.x >> 4;
    const int b0 = mt * 256;
    const int j0 = nt * 64;
    const int k_base = ks * 4096;
    const int h_base = ks * 32;

    float* s_left = (float*)(smem + LEFT_OFF);

    // ---- stage left slab [256][32] (pitch 33) ----
    #pragma unroll
    for (int u = 0; u < 4; ++u) {
        int id = u * 512 + t;                 // 2048 float4
        int r = id >> 3, c4 = id & 7;
        float4 v = *(const float4*)(left + (size_t)(b0 + r) * 256 + h_base + c4 * 4);
        float* dp = s_left + r * 33 + c4 * 4;
        dp[0] = v.x; dp[1] = v.y; dp[2] = v.z; dp[3] = v.w;
    }

    // ---- x3 -> registers as h2 (thread owns row t>>1, k-sub t&1) ----
    const int ar_row = t >> 1, ar_sub = t & 1;
    uint32_t xr[2][16];
    {
        const float* xsrc = x3g + (size_t)(b0 + ar_row) * 128 + ar_sub * 32;
        #pragma unroll
        for (int R = 0; R < 2; ++R)
            #pragma unroll
            for (int u = 0; u < 8; ++u) {
                float4 v = *(const float4*)(xsrc + R * 64 + u * 4);
                xr[R][u * 2]     = h2bits(__floats2half2_rn(v.x, v.y));
                xr[R][u * 2 + 1] = h2bits(__floats2half2_rn(v.z, v.w));
            }
    }
    __syncthreads();

    // ---- producer state ----
    const int wr_row = t >> 3;          // 0..63 (n row)
    const int wr_c4  = t & 7;           // 0..7  (16B column)
    const float* wsrc_base = wf + (size_t)(j0 + wr_row) * 32768 + k_base + wr_c4 * 8;
    const uint32_t w_soff = SWZ(wr_row * 128 + wr_c4 * 16);
    float wreg[8];

    #define LDG_W(c) do {                                                        \
        const float4* p = (const float4*)(wsrc_base + (c) * 64);                 \
        float4 v0 = p[0], v1 = p[1];                                             \
        wreg[0]=v0.x; wreg[1]=v0.y; wreg[2]=v0.z; wreg[3]=v0.w;                  \
        wreg[4]=v1.x; wreg[5]=v1.y; wreg[6]=v1.z; wreg[7]=v1.w;                  \
    } while (0)

    #define STS_W(s2) do {                                                       \
        uint32_t hiw[4], low[4];                                                 \
        _Pragma("unroll")                                                        \
        for (int e = 0; e < 4; ++e) {                                            \
            float f0 = wreg[2*e], f1 = wreg[2*e+1];                              \
            __half ha = __float2half_rn(f0), hb = __float2half_rn(f1);           \
            __half la = __float2half_rn(f0 - __half2float(ha));                  \
            __half lb = __float2half_rn(f1 - __half2float(hb));                  \
            hiw[e] = h2bits(__halves2half2(ha, hb));                             \
            low[e] = h2bits(__halves2half2(la, lb));                             \
        }                                                                        \
        *(uint4*)(smem + (s2)*ST_BYTES + WHI_OFF + w_soff) =                     \
            make_uint4(hiw[0], hiw[1], hiw[2], hiw[3]);                          \
        *(uint4*)(smem + (s2)*ST_BYTES + WLO_OFF + w_soff) =                     \
            make_uint4(low[0], low[1], low[2], low[3]);                          \
    } while (0)

    #define GEN_A(c, s2) do {                                                    \
        const float L = s_left[ar_row * 33 + ((c) >> 1)];                        \
        const uint32_t* xp = xr[(c) & 1];                                        \
        char* ab = smem + (s2) * ST_BYTES + A_OFF;                               \
        _Pragma("unroll")                                                        \
        for (int g = 0; g < 4; ++g) {                                            \
            uint32_t o[4];                                                       \
            _Pragma("unroll")                                                    \
            for (int m = 0; m < 4; ++m) {                                        \
                float2 xf = __half22float2(*(__half2*)&xp[g * 4 + m]);           \
                o[m] = h2bits(__floats2half2_rn(L * xf.x, L * xf.y));            \
            }                                                                    \
            int off = ar_row * 128 + ar_sub * 64 + g * 16;                       \
            *(uint4*)(ab + SWZ(off)) = make_uint4(o[0], o[1], o[2], o[3]);       \
        }                                                                        \
    } while (0)

    // ---- consumer state ----
    const int wid = t >> 5, l = t & 31;
    const int mw = wid & 3;          // M-warp: rows mw*64..+64
    const int nw = wid >> 2;         // N-warp: cols nw*16..+16
    const uint32_t lrow = (uint32_t)(l & 15);
    const uint32_t lkb  = (uint32_t)((l >> 4) * 16);
    float d[4][2][4];
    #pragma unroll
    for (int mi = 0; mi < 4; ++mi)
        #pragma unroll
        for (int ni = 0; ni < 2; ++ni)
            #pragma unroll
            for (int e = 0; e < 4; ++e) d[mi][ni][e] = 0.0f;

    // ---- prologue: chunks 0,1 direct; prefetch chunk 2 ----
    LDG_W(0); STS_W(0); GEN_A(0, 0);
    LDG_W(1); STS_W(1); GEN_A(1, 1);
    LDG_W(2);

    // ---- mainloop: one barrier per chunk ----
    for (int c = 0; c < 64; ++c) {
        const int s = c % 3;
        __syncthreads();

        const uint32_t aB = smb + s * ST_BYTES + A_OFF;
        const uint32_t hB = smb + s * ST_BYTES + WHI_OFF;
        const uint32_t lB = smb + s * ST_BYTES + WLO_OFF;

        #pragma unroll
        for (int st = 0; st < 4; ++st) {
            const uint32_t kb = st * 32 + lkb;
            uint32_t bh[4], bl[4];
            {
                uint32_t off = (nw * 16 + lrow) * 128 + kb;
                LDSM_X4(bh, hB + SWZ(off));
                LDSM_X4(bl, lB + SWZ(off));
            }
            #pragma unroll
            for (int mi = 0; mi < 4; ++mi) {
                uint32_t a[4];
                uint32_t off = (mw * 64 + mi * 16 + lrow) * 128 + kb;
                LDSM_X4(a, aB + SWZ(off));
                #pragma unroll
                for (int ni = 0; ni < 2; ++ni) {
                    MMA16816(d[mi][ni], a, bh[ni], bh[ni + 2]);
                    MMA16816(d[mi][ni], a, bl[ni], bl[ni + 2]);
                }
            }
        }

        const int cn = c + 2;
        if (cn < 64) {
            const int s2 = cn % 3;
            STS_W(s2);           // wreg holds chunk cn (loaded last iter / prologue)
            GEN_A(cn, s2);
            if (cn + 1 < 64) LDG_W(cn + 1);
        }
    }

    // ---- epilogue: write fp32 partials ----
    {
        float* op = part + (size_t)ks * (B_ * H_);
        const int rb = b0 + mw * 64;
        const int cb = j0 + nw * 16;
        #pragma unroll
        for (int mi = 0; mi < 4; ++mi)
            #pragma unroll
            for (int ni = 0; ni < 2; ++ni) {
                int row = rb + mi * 16 + (l >> 2);
                int col = cb + ni * 8 + (l & 3) * 2;
                *(float2*)(op + (size_t)row * 256 + col) =
                    make_float2(d[mi][ni][0], d[mi][ni][1]);
                *(float2*)(op + (size_t)(row + 8) * 256 + col) =
                    make_float2(d[mi][ni][2], d[mi][ni][3]);
            }
    }
    #undef LDG_W
    #undef STS_W
    #undef GEN_A
}

// ---------------------------------------------------------------------------
// Split-K reduction over 8 partials (+ optional tanh)
// ---------------------------------------------------------------------------
template <bool TANH>
__global__ __launch_bounds__(256) void reduce8(
    const float* __restrict__ part, float* __restrict__ outp)
{
    const int total4 = (B_ * H_) / 4;   // 65536
    for (int i = blockIdx.x * blockDim.x + threadIdx.x; i < total4;
         i += gridDim.x * blockDim.x) {
        float4 r = ((const float4*)part)[i];
        #pragma unroll
        for (int s = 1; s < NSPLIT; ++s) {
            float4 v = ((const float4*)part)[i + s * 65536];
            r.x += v.x; r.y += v.y; r.z += v.z; r.w += v.w;
        }
        if (TANH) { r.x = tanhf(r.x); r.y = tanhf(r.y); r.z = tanhf(r.z); r.w = tanhf(r.w); }
        ((float4*)outp)[i] = r;
    }
}

// ---------------------------------------------------------------------------
extern "C" void kernel_launch(void* const* d_in, const int* in_sizes, int n_in,
                              void* d_out, int out_size)
{
    const float* h0  = (const float*)d_in[0];
    const float* ht  = (const float*)d_in[1];
    const float* msg = (const float*)d_in[2];
    const float* cp  = (const float*)d_in[3];
    const float* fc1 = (const float*)d_in[4];
    const float* fc2 = (const float*)d_in[5];
    const float* fc3 = (const float*)d_in[6];
    const float* fc4 = (const float*)d_in[7];
    float*       outp = (float*)d_out;

    float* x3p;  cudaGetSymbolAddress((void**)&x3p, g_x3);
    float* g1p;  cudaGetSymbolAddress((void**)&g1p, g_g1out);
    float* pp;   cudaGetSymbolAddress((void**)&pp,  g_part);

    cudaFuncSetAttribute(hyper_gemm, cudaFuncAttributeMaxDynamicSharedMemorySize,
                         GEMM_SMEM);

    // tanh chain -> x3
    prep_kernel<<<256, 128>>>(h0, ht, cp, fc1, fc2, fc3, x3p);
    // Phase A: g1_out = tanh(msg,x3 : W1)
    hyper_gemm<<<128, 512, GEMM_SMEM>>>(msg, x3p, fc4, pp);
    reduce8<true><<<256, 256>>>(pp, g1p);
    // Phase B: out = (g1_out,x3 : W2)
    hyper_gemm<<<128, 512, GEMM_SMEM>>>(g1p, x3p, fc4 + (size_t)PHASE_W, pp);
    reduce8<false><<<256, 256>>>(pp, outp);
}